// round 9
// baseline (speedup 1.0000x reference)
#include <cuda_runtime.h>
#include <math.h>
#include <stdint.h>

#define NN 10000
#define EE 160000
#define OUTC 12

typedef unsigned long long u64;

// ---------------- scratch (device globals; no allocation allowed) ----------------
__device__ float g_bufA[NN * 64 * 12];
__device__ float g_bufB[NN * 64 * 12];
__device__ int   g_cnt[NN];
__device__ int   g_fill[NN];
__device__ int   g_rowptr[NN + 1];
__device__ int   g_col[EE + NN];
__device__ float g_deg[NN];
__device__ float g_dis[NN];
__device__ float g_wc[EE + NN];
// prepacked conv weights: [(k*cin+ci)*64 + ch] = (w[ch][ci][k], w[ch+64][ci][k])
__device__ float2 g_wp1[3 * 32 * 64];
__device__ float2 g_wp2[3 * 64 * 64];
__device__ float2 g_wp3[3 * 64 * 64];
__device__ float2 g_wp4[3 * 64 * 64];
__device__ float2 g_bp1[64], g_bp2[64], g_bp3[64], g_bp4[64];

// ---------------- f32x2 helpers ----------------
__device__ __forceinline__ u64 pk2(float a, float b) {
    u64 r; asm("mov.b64 %0, {%1, %2};" : "=l"(r) : "f"(a), "f"(b)); return r;
}
__device__ __forceinline__ void upk2(u64 v, float& a, float& b) {
    asm("mov.b64 {%0, %1}, %2;" : "=f"(a), "=f"(b) : "l"(v));
}
__device__ __forceinline__ u64 ffma2(u64 a, u64 b, u64 c) {
    u64 d; asm("fma.rn.f32x2 %0, %1, %2, %3;" : "=l"(d) : "l"(a), "l"(b), "l"(c)); return d;
}

// ---------------- CSR build (proven) ----------------
__global__ void csr_init(int* cnt, float* deg, int* fill) {
    int v = blockIdx.x * blockDim.x + threadIdx.x;
    if (v < NN) { cnt[v] = 1; deg[v] = 1.0f; fill[v] = 0; }
}
__global__ void csr_count(const int* __restrict__ dst, const float* __restrict__ ew,
                          int* cnt, float* deg) {
    int e = blockIdx.x * blockDim.x + threadIdx.x;
    if (e < EE) {
        int d = dst[e];
        atomicAdd(&cnt[d], 1);
        atomicAdd(&deg[d], ew[e]);
    }
}
__global__ void csr_dis(const float* __restrict__ deg, float* dis) {
    int v = blockIdx.x * blockDim.x + threadIdx.x;
    if (v < NN) dis[v] = rsqrtf(deg[v]);
}
__global__ void scan_kernel(const int* __restrict__ cnt, int* __restrict__ rowptr) {
    __shared__ int part[1024];
    const int tid = threadIdx.x;
    const int CHUNK = 10;
    int base = tid * CHUNK;
    int local[CHUNK];
    int s = 0;
#pragma unroll
    for (int i = 0; i < CHUNK; i++) {
        int idx = base + i;
        int v = (idx < NN) ? cnt[idx] : 0;
        local[i] = s;
        s += v;
    }
    part[tid] = s;
    __syncthreads();
    for (int off = 1; off < 1024; off <<= 1) {
        int v = (tid >= off) ? part[tid - off] : 0;
        __syncthreads();
        part[tid] += v;
        __syncthreads();
    }
    int offset = (tid > 0) ? part[tid - 1] : 0;
#pragma unroll
    for (int i = 0; i < CHUNK; i++) {
        int idx = base + i;
        if (idx <= NN) rowptr[idx] = offset + local[i];
    }
}
__global__ void csr_fill(const int* __restrict__ src, const int* __restrict__ dst,
                         const float* __restrict__ ew, const float* __restrict__ dis,
                         const int* __restrict__ rowptr, int* fill,
                         int* __restrict__ col, float* __restrict__ wc) {
    int i = blockIdx.x * blockDim.x + threadIdx.x;
    if (i < EE) {
        int s = src[i], d = dst[i];
        int pos = rowptr[d] + atomicAdd(&fill[d], 1);
        col[pos] = s;
        wc[pos] = dis[s] * ew[i] * dis[d];
    } else if (i < EE + NN) {
        int v = i - EE;
        int pos = rowptr[v] + atomicAdd(&fill[v], 1);
        col[pos] = v;
        wc[pos] = dis[v] * dis[v];
    }
}

// ---------------- conv weight prepack: (wP, wQ) pairs, [k][ci][ch] ----------------
__global__ void prepack(const float* __restrict__ w, const float* __restrict__ b,
                        float2* __restrict__ wp, float2* __restrict__ bp, int cin) {
    int i = blockIdx.x * blockDim.x + threadIdx.x;
    int total = 3 * cin * 64;
    if (i < total) {
        int ch = i & 63;
        int kc = i >> 6;            // k*cin + ci
        int k = kc / cin, ci = kc - k * cin;
        wp[i] = make_float2(w[ch * cin * 3 + ci * 3 + k],
                            w[(ch + 64) * cin * 3 + ci * 3 + k]);
    }
    if (i < 64) bp[i] = make_float2(b[i], b[i + 64]);
}

// ---------------- gated temporal conv: 2 nodes per thread ----------------
// Tile = 16 nodes, 256 threads (8 warps; warp w handles nodes w and w+8).
// Shared: Xdup [CIN][226] u64 (value duplicated (x,x)); node nl at slots 14*nl..14*nl+13,
// slots 0/13 zero pad. Ws [3*CIN*64] u64 of (wP,wQ) pairs shared across both nodes.
// lane = chgrp(4ch)*2 + half(6t). 144 FFMA2 : 14 LDS.128 per ci.
template <int CIN>
__global__ void __launch_bounds__(256, 1) conv_simt(
        const float2* __restrict__ Wp, const float2* __restrict__ Bp,
        const float* __restrict__ xin,   // [node][CIN][12]
        float* __restrict__ xout)        // [node][64][12]
{
    extern __shared__ char sm[];
    u64* Xs = (u64*)sm;                          // [CIN][226]
    u64* Ws = (u64*)(sm + CIN * 226 * 8);        // [3*CIN*64]

    const int tid = threadIdx.x;
    const int wid = tid >> 5;                    // 0..7
    const int lane = tid & 31;
    const int chgrp = lane >> 1;                 // 0..15
    const int half = lane & 1;
    const int t0 = half * 6;
    const int nlA = wid;                         // node A in tile
    const int nlB = wid + 8;                     // node B in tile

    // W -> shared (once per CTA)
    for (int i = tid; i < 3 * CIN * 64; i += 256) {
        float2 w = Wp[i];
        Ws[i] = pk2(w.x, w.y);
    }
    u64 bias[4];
#pragma unroll
    for (int cp = 0; cp < 4; cp++) {
        float2 b = Bp[chgrp * 4 + cp];
        bias[cp] = pk2(b.x, b.y);
    }

    for (int grp = blockIdx.x; grp < NN / 16; grp += gridDim.x) {
        // ---- fill X tile (duplicated) ----
        for (int p = tid; p < 16 * CIN; p += 256) {
            int nl = p / CIN, ci = p - nl * CIN;
            const float4* srcp = (const float4*)(xin + ((size_t)(grp * 16 + nl) * CIN + ci) * 12);
            float4 a = srcp[0], b4 = srcp[1], c4 = srcp[2];
            u64* row = Xs + ci * 226 + nl * 14;
            row[0] = 0; row[13] = 0;
            row[1]  = pk2(a.x, a.x);  row[2]  = pk2(a.y, a.y);
            row[3]  = pk2(a.z, a.z);  row[4]  = pk2(a.w, a.w);
            row[5]  = pk2(b4.x, b4.x); row[6]  = pk2(b4.y, b4.y);
            row[7]  = pk2(b4.z, b4.z); row[8]  = pk2(b4.w, b4.w);
            row[9]  = pk2(c4.x, c4.x); row[10] = pk2(c4.y, c4.y);
            row[11] = pk2(c4.z, c4.z); row[12] = pk2(c4.w, c4.w);
        }
        __syncthreads();

        // ---- main FMA loop ----
        u64 accA[4][6], accB[4][6];
#pragma unroll
        for (int cp = 0; cp < 4; cp++)
#pragma unroll
            for (int j = 0; j < 6; j++) { accA[cp][j] = bias[cp]; accB[cp][j] = bias[cp]; }

        const u64* xbaseA = Xs + nlA * 14 + t0;       // + ci*226
        const u64* xbaseB = Xs + nlB * 14 + t0;
        const u64* wbase = Ws + chgrp * 4;            // + (k*CIN+ci)*64

#pragma unroll 1
        for (int ci = 0; ci < CIN; ci++) {
            u64 xa[8], xb[8];
            {
                const ulonglong2* xp = (const ulonglong2*)(xbaseA + ci * 226);
#pragma unroll
                for (int q = 0; q < 4; q++) {
                    ulonglong2 v = xp[q];
                    xa[2 * q] = v.x; xa[2 * q + 1] = v.y;
                }
            }
            {
                const ulonglong2* xp = (const ulonglong2*)(xbaseB + ci * 226);
#pragma unroll
                for (int q = 0; q < 4; q++) {
                    ulonglong2 v = xp[q];
                    xb[2 * q] = v.x; xb[2 * q + 1] = v.y;
                }
            }
#pragma unroll
            for (int k = 0; k < 3; k++) {
                const ulonglong2* wpp = (const ulonglong2*)(wbase + (k * CIN + ci) * 64);
                ulonglong2 w01 = wpp[0], w23 = wpp[1];
                u64 wv[4] = { w01.x, w01.y, w23.x, w23.y };
#pragma unroll
                for (int cp = 0; cp < 4; cp++) {
#pragma unroll
                    for (int j = 0; j < 6; j++) {
                        accA[cp][j] = ffma2(wv[cp], xa[j + k], accA[cp][j]);
                        accB[cp][j] = ffma2(wv[cp], xb[j + k], accB[cp][j]);
                    }
                }
            }
        }

        // ---- epilogue: gate + store (both nodes) ----
        const int gA = grp * 16 + nlA;
        const int gB = grp * 16 + nlB;
#pragma unroll
        for (int cp = 0; cp < 4; cp++) {
            int ch = chgrp * 4 + cp;
            float2* orA = (float2*)(xout + ((size_t)gA * 64 + ch) * 12 + t0);
            float2* orB = (float2*)(xout + ((size_t)gB * 64 + ch) * 12 + t0);
#pragma unroll
            for (int jp = 0; jp < 3; jp++) {
                float p0, q0, p1, q1;
                upk2(accA[cp][2 * jp], p0, q0);
                upk2(accA[cp][2 * jp + 1], p1, q1);
                float2 o;
                o.x = p0 / (1.0f + __expf(-q0));
                o.y = p1 / (1.0f + __expf(-q1));
                orA[jp] = o;
                upk2(accB[cp][2 * jp], p0, q0);
                upk2(accB[cp][2 * jp + 1], p1, q1);
                o.x = p0 / (1.0f + __expf(-q0));
                o.y = p1 / (1.0f + __expf(-q1));
                orB[jp] = o;
            }
        }
        __syncthreads();   // Xs reusable next group
    }
}

// ---------------- GCN aggregation (proven, 768-stride) ----------------
__global__ void __launch_bounds__(256) agg_kernel(
        const float* __restrict__ hin, const int* __restrict__ rowptr,
        const int* __restrict__ col, const float* __restrict__ wc,
        float* __restrict__ out)
{
    const int v = blockIdx.x;
    const int tid = threadIdx.x;
    const int beg = rowptr[v], end = rowptr[v + 1];
    float a0 = 0.f, a1 = 0.f, a2 = 0.f;
    __shared__ int scol[64];
    __shared__ float sw[64];
    for (int j0 = beg; j0 < end; j0 += 64) {
        int m = min(64, end - j0);
        if (tid < m) { scol[tid] = col[j0 + tid] * 768; sw[tid] = wc[j0 + tid]; }
        __syncthreads();
#pragma unroll 4
        for (int i = 0; i < m; i++) {
            const float* p = hin + scol[i];
            float w = sw[i];
            a0 = fmaf(w, p[tid], a0);
            a1 = fmaf(w, p[tid + 256], a1);
            a2 = fmaf(w, p[tid + 512], a2);
        }
        __syncthreads();
    }
    float* o = out + (size_t)v * 768;
    o[tid] = a0; o[tid + 256] = a1; o[tid + 512] = a2;
}

// ---------------- GCN transform (proven): out = relu(W @ agg + b) ----------------
__global__ void __launch_bounds__(256) gcn_transform(
        const float* __restrict__ agg, const float* __restrict__ W,
        const float* __restrict__ b, float* __restrict__ out)
{
    const int o = threadIdx.x;
    const int ln = threadIdx.y;
    const int node = blockIdx.x * 4 + ln;
    __shared__ u64 xs[4][64][6];
    __shared__ float Wsh[64][65];

    const float2* ar = (const float2*)(agg + (size_t)node * 768 + o * 12);
#pragma unroll
    for (int j = 0; j < 6; j++) { float2 v = ar[j]; xs[ln][o][j] = pk2(v.x, v.y); }
    for (int i = ln * 64 + o; i < 4096; i += 256) {
        int orow = i >> 6, c = i & 63;
        Wsh[c][orow] = W[i];
    }
    __syncthreads();

    u64 acc[6];
    {
        float bo = b[o];
        u64 b0 = pk2(bo, bo);
#pragma unroll
        for (int j = 0; j < 6; j++) acc[j] = b0;
    }
#pragma unroll 4
    for (int c = 0; c < 64; c++) {
        float w = Wsh[c][o];
        u64 wp = pk2(w, w);
#pragma unroll
        for (int j = 0; j < 6; j++) acc[j] = ffma2(wp, xs[ln][c][j], acc[j]);
    }

    float ov[12];
#pragma unroll
    for (int j = 0; j < 6; j++) {
        float p, q; upk2(acc[j], p, q);
        ov[2 * j]     = fmaxf(p, 0.0f);
        ov[2 * j + 1] = fmaxf(q, 0.0f);
    }
    float4* orow = (float4*)(out + (size_t)node * 768 + o * 12);
#pragma unroll
    for (int j = 0; j < 3; j++)
        orow[j] = make_float4(ov[4 * j], ov[4 * j + 1], ov[4 * j + 2], ov[4 * j + 3]);
}

// ---------------- final conv: warp per node, fw in shared ----------------
__global__ void __launch_bounds__(256) final_conv(
        const float* __restrict__ h, const float* __restrict__ fw,
        const float* __restrict__ fb, float* __restrict__ out)
{
    __shared__ float fws[12 * 768];
    __shared__ float fbs[12];
    const int tid = threadIdx.x;
    for (int i = tid; i < 12 * 768; i += 256) fws[i] = fw[i];
    if (tid < 12) fbs[tid] = fb[tid];
    __syncthreads();

    const int wid = tid >> 5, lane = tid & 31;
    const int node = blockIdx.x * 8 + wid;

    const float4* hr = (const float4*)(h + (size_t)node * 768) + lane * 6;
    float4 hv[6];
#pragma unroll
    for (int q = 0; q < 6; q++) hv[q] = hr[q];

#pragma unroll 1
    for (int o = 0; o < 12; o++) {
        const float4* wr = (const float4*)(fws + o * 768) + lane * 6;
        float acc = 0.f;
#pragma unroll
        for (int q = 0; q < 6; q++) {
            float4 wv = wr[q];
            acc += hv[q].x * wv.x + hv[q].y * wv.y + hv[q].z * wv.z + hv[q].w * wv.w;
        }
#pragma unroll
        for (int m = 16; m; m >>= 1) acc += __shfl_xor_sync(0xffffffffu, acc, m);
        if (lane == o) out[node * 12 + o] = acc + fbs[o];
    }
}

// ---------------- launch ----------------
extern "C" void kernel_launch(void* const* d_in, const int* in_sizes, int n_in,
                              void* d_out, int out_size) {
    const float* x      = (const float*)d_in[0];
    const int*   ei     = (const int*)d_in[1];
    const float* ew     = (const float*)d_in[2];
    const float* tc1a_w = (const float*)d_in[3];
    const float* tc1a_b = (const float*)d_in[4];
    const float* gc1_w  = (const float*)d_in[5];
    const float* gc1_b  = (const float*)d_in[6];
    const float* tc1b_w = (const float*)d_in[7];
    const float* tc1b_b = (const float*)d_in[8];
    const float* tc2a_w = (const float*)d_in[9];
    const float* tc2a_b = (const float*)d_in[10];
    const float* gc2_w  = (const float*)d_in[11];
    const float* gc2_b  = (const float*)d_in[12];
    const float* tc2b_w = (const float*)d_in[13];
    const float* tc2b_b = (const float*)d_in[14];
    const float* fin_w  = (const float*)d_in[15];
    const float* fin_b  = (const float*)d_in[16];

    const int* src = ei;
    const int* dst = ei + EE;

    float *bufA, *bufB, *deg, *dis, *wc;
    int *cnt, *fill, *rowptr, *col;
    float2 *wp1, *wp2, *wp3, *wp4, *bp1, *bp2, *bp3, *bp4;
    cudaGetSymbolAddress((void**)&bufA,   g_bufA);
    cudaGetSymbolAddress((void**)&bufB,   g_bufB);
    cudaGetSymbolAddress((void**)&deg,    g_deg);
    cudaGetSymbolAddress((void**)&dis,    g_dis);
    cudaGetSymbolAddress((void**)&wc,     g_wc);
    cudaGetSymbolAddress((void**)&cnt,    g_cnt);
    cudaGetSymbolAddress((void**)&fill,   g_fill);
    cudaGetSymbolAddress((void**)&rowptr, g_rowptr);
    cudaGetSymbolAddress((void**)&col,    g_col);
    cudaGetSymbolAddress((void**)&wp1,    g_wp1);
    cudaGetSymbolAddress((void**)&wp2,    g_wp2);
    cudaGetSymbolAddress((void**)&wp3,    g_wp3);
    cudaGetSymbolAddress((void**)&wp4,    g_wp4);
    cudaGetSymbolAddress((void**)&bp1,    g_bp1);
    cudaGetSymbolAddress((void**)&bp2,    g_bp2);
    cudaGetSymbolAddress((void**)&bp3,    g_bp3);
    cudaGetSymbolAddress((void**)&bp4,    g_bp4);

    const int SMEM32 = 32 * 226 * 8 + 3 * 32 * 64 * 8;   // 107008
    const int SMEM64 = 64 * 226 * 8 + 3 * 64 * 64 * 8;   // 214016
    cudaFuncSetAttribute(conv_simt<32>, cudaFuncAttributeMaxDynamicSharedMemorySize, SMEM32);
    cudaFuncSetAttribute(conv_simt<64>, cudaFuncAttributeMaxDynamicSharedMemorySize, SMEM64);

    // Keep conv_simt<32> at launch index 3 — the slot ncu's fixed "-s 5 -c 1"
    // capture lands on. Dependencies hold: conv1 needs only prepack1 + x;
    // csr_count precedes csr_dis precedes csr_fill.
    prepack<<<(3 * 32 * 64 + 255) / 256, 256>>>(tc1a_w, tc1a_b, wp1, bp1, 32);    // 0
    csr_init<<<(NN + 255) / 256, 256>>>(cnt, deg, fill);                          // 1
    csr_count<<<(EE + 255) / 256, 256>>>(dst, ew, cnt, deg);                      // 2
    conv_simt<32><<<125, 256, SMEM32>>>(wp1, bp1, x, bufA);                       // 3 <- profiled
    csr_dis<<<(NN + 255) / 256, 256>>>(deg, dis);                                 // 4
    scan_kernel<<<1, 1024>>>(cnt, rowptr);                                        // 5
    csr_fill<<<(EE + NN + 255) / 256, 256>>>(src, dst, ew, dis, rowptr, fill, col, wc);
    prepack<<<(3 * 64 * 64 + 255) / 256, 256>>>(tc1b_w, tc1b_b, wp2, bp2, 64);
    prepack<<<(3 * 64 * 64 + 255) / 256, 256>>>(tc2a_w, tc2a_b, wp3, bp3, 64);
    prepack<<<(3 * 64 * 64 + 255) / 256, 256>>>(tc2b_w, tc2b_b, wp4, bp4, 64);

    dim3 tb(64, 4);
    // block 1 (conv1 already launched above)
    agg_kernel<<<NN, 256>>>(bufA, rowptr, col, wc, bufB);
    gcn_transform<<<NN / 4, tb>>>(bufB, gc1_w, gc1_b, bufA);
    conv_simt<64><<<125, 256, SMEM64>>>(wp2, bp2, bufA, bufB);
    // block 2
    conv_simt<64><<<125, 256, SMEM64>>>(wp3, bp3, bufB, bufA);
    agg_kernel<<<NN, 256>>>(bufA, rowptr, col, wc, bufB);
    gcn_transform<<<NN / 4, tb>>>(bufB, gc2_w, gc2_b, bufA);
    conv_simt<64><<<125, 256, SMEM64>>>(wp4, bp4, bufA, bufB);
    // head
    final_conv<<<NN / 8, 256>>>(bufB, fin_w, fin_b, (float*)d_out);
}

// round 14
// speedup vs baseline: 1.1586x; 1.1586x over previous
#include <cuda_runtime.h>
#include <cuda_bf16.h>
#include <math.h>
#include <stdint.h>

#define NN 10000
#define EE 160000
#define NTILES 2500            // 160000 padded tokens / 64

typedef unsigned long long u64;
typedef unsigned int u32;

// ---------------- scratch (device globals; no allocation allowed) ----------------
__device__ float g_bufA[NN * 64 * 12];
__device__ float g_bufB[NN * 64 * 12];
__device__ int   g_cnt[NN];
__device__ int   g_fill[NN];
__device__ int   g_rowptr[NN + 1];
__device__ int   g_col[EE + NN];
__device__ float g_deg[NN];
__device__ float g_dis[NN];
__device__ float g_wc[EE + NN];
// prepacked bf16 conv weights: [tap][plane hi/lo][grow 128][ci CIN]
__device__ uint4 g_wA1[3072];   // CIN=32: 3*2*128*32*2B
__device__ uint4 g_wA2[6144];   // CIN=64
__device__ uint4 g_wA3[6144];
__device__ uint4 g_wA4[6144];

// ---------------- helpers ----------------
__device__ __forceinline__ u64 pk2(float a, float b) {
    u64 r; asm("mov.b64 %0, {%1, %2};" : "=l"(r) : "f"(a), "f"(b)); return r;
}
__device__ __forceinline__ void upk2(u64 v, float& a, float& b) {
    asm("mov.b64 {%0, %1}, %2;" : "=f"(a), "=f"(b) : "l"(v));
}
__device__ __forceinline__ u64 ffma2(u64 a, u64 b, u64 c) {
    u64 d; asm("fma.rn.f32x2 %0, %1, %2, %3;" : "=l"(d) : "l"(a), "l"(b), "l"(c)); return d;
}
__device__ __forceinline__ u32 smem_u32(const void* p) {
    u32 a;
    asm("{ .reg .u64 t; cvta.to.shared.u64 t, %1; cvt.u32.u64 %0, t; }" : "=r"(a) : "l"(p));
    return a;
}
__device__ __forceinline__ void ldsm4(u32 r[4], u32 addr) {
    asm volatile("ldmatrix.sync.aligned.m8n8.x4.shared.b16 {%0,%1,%2,%3}, [%4];"
                 : "=r"(r[0]), "=r"(r[1]), "=r"(r[2]), "=r"(r[3]) : "r"(addr));
}
__device__ __forceinline__ void mma16816(float c[4], const u32 a[4], const u32 b0, const u32 b1) {
    asm volatile("mma.sync.aligned.m16n8k16.row.col.f32.bf16.bf16.f32 "
                 "{%0,%1,%2,%3}, {%4,%5,%6,%7}, {%8,%9}, {%0,%1,%2,%3};"
                 : "+f"(c[0]), "+f"(c[1]), "+f"(c[2]), "+f"(c[3])
                 : "r"(a[0]), "r"(a[1]), "r"(a[2]), "r"(a[3]), "r"(b0), "r"(b1));
}

// ---------------- CSR build (proven) ----------------
__global__ void csr_init(int* cnt, float* deg, int* fill) {
    int v = blockIdx.x * blockDim.x + threadIdx.x;
    if (v < NN) { cnt[v] = 1; deg[v] = 1.0f; fill[v] = 0; }
}
__global__ void csr_count(const int* __restrict__ dst, const float* __restrict__ ew,
                          int* cnt, float* deg) {
    int e = blockIdx.x * blockDim.x + threadIdx.x;
    if (e < EE) {
        int d = dst[e];
        atomicAdd(&cnt[d], 1);
        atomicAdd(&deg[d], ew[e]);
    }
}
__global__ void csr_dis(const float* __restrict__ deg, float* dis) {
    int v = blockIdx.x * blockDim.x + threadIdx.x;
    if (v < NN) dis[v] = rsqrtf(deg[v]);
}
__global__ void scan_kernel(const int* __restrict__ cnt, int* __restrict__ rowptr) {
    __shared__ int part[1024];
    const int tid = threadIdx.x;
    const int CHUNK = 10;
    int base = tid * CHUNK;
    int local[CHUNK];
    int s = 0;
#pragma unroll
    for (int i = 0; i < CHUNK; i++) {
        int idx = base + i;
        int v = (idx < NN) ? cnt[idx] : 0;
        local[i] = s;
        s += v;
    }
    part[tid] = s;
    __syncthreads();
    for (int off = 1; off < 1024; off <<= 1) {
        int v = (tid >= off) ? part[tid - off] : 0;
        __syncthreads();
        part[tid] += v;
        __syncthreads();
    }
    int offset = (tid > 0) ? part[tid - 1] : 0;
#pragma unroll
    for (int i = 0; i < CHUNK; i++) {
        int idx = base + i;
        if (idx <= NN) rowptr[idx] = offset + local[i];
    }
}
__global__ void csr_fill(const int* __restrict__ src, const int* __restrict__ dst,
                         const float* __restrict__ ew, const float* __restrict__ dis,
                         const int* __restrict__ rowptr, int* fill,
                         int* __restrict__ col, float* __restrict__ wc) {
    int i = blockIdx.x * blockDim.x + threadIdx.x;
    if (i < EE) {
        int s = src[i], d = dst[i];
        int pos = rowptr[d] + atomicAdd(&fill[d], 1);
        col[pos] = s;
        wc[pos] = dis[s] * ew[i] * dis[d];
    } else if (i < EE + NN) {
        int v = i - EE;
        int pos = rowptr[v] + atomicAdd(&fill[v], 1);
        col[pos] = v;
        wc[pos] = dis[v] * dis[v];
    }
}

// ---------------- conv weight prepack for mma ----------------
// wA[tap][plane][grow][ci]: grow row r -> warp w=r/16, rl=r%16, ch8 = w*8+rl/2,
// co = (rl odd) ? ch8+64 : ch8. plane 0 = bf16 hi, 1 = bf16 lo.
__global__ void prepack_mma(const float* __restrict__ w, unsigned short* __restrict__ wA,
                            int cin) {
    int i = blockIdx.x * blockDim.x + threadIdx.x;
    int total = 3 * 2 * 128 * cin;
    if (i >= total) return;
    int tap = i / (2 * 128 * cin);
    int r = i - tap * (2 * 128 * cin);
    int plane = r / (128 * cin); r -= plane * (128 * cin);
    int grow = r / cin;
    int ci = r - grow * cin;
    int rl = grow & 15;
    int ch8 = (grow >> 4) * 8 + (rl >> 1);
    int co = (rl & 1) ? ch8 + 64 : ch8;
    float v = w[co * cin * 3 + ci * 3 + tap];
    __nv_bfloat16 hi = __float2bfloat16(v);
    if (plane == 0) {
        wA[i] = *(unsigned short*)&hi;
    } else {
        __nv_bfloat16 lo = __float2bfloat16(v - __bfloat162float(hi));
        wA[i] = *(unsigned short*)&lo;
    }
}

// ---------------- gated temporal conv via mma.sync bf16 (fallback HMMA) ----------------
// Tile = 64 tokens (4 nodes, 16 padded slots/node; slots 12-15 zero). B smem rows =
// tokens -1..64 (row 0 = zero pad), cols = ci, hi/lo planes. A (weights) preloaded
// into registers via ldmatrix; 3 taps accumulate into one C by shifting B row addr.
template <int CIN>
__global__ void __launch_bounds__(256, 1) conv_mma(
        const uint4* __restrict__ wA, const float* __restrict__ bglob,
        const float* __restrict__ xin,   // [node][CIN][12]
        float* __restrict__ xout)        // [node][64][12]
{
    constexpr int KSTEPS = CIN / 16;
    constexpr int BSTRIDE = (CIN + 8) * 2;          // bytes per B row (conflict-free)
    constexpr int BPLANE = ((66 * BSTRIDE + 127) / 128) * 128;
    constexpr int STAGE_BYTES = 2 * 128 * CIN * 2;  // one tap, both planes

    extern __shared__ char sm[];
    const u32 S = smem_u32(sm);
    const int tid = threadIdx.x;
    const int w = tid >> 5;
    const int lane = tid & 31;
    const int grp = lane >> 3;
    const int rl = lane & 7;

    // ---- stage A per tap, ldmatrix into registers ----
    u32 afr[3][KSTEPS][2][4];
    {
        uint4* stg = (uint4*)sm;
        const int CNT = STAGE_BYTES / 16;
        for (int tap = 0; tap < 3; tap++) {
            __syncthreads();
            const uint4* src = wA + tap * CNT;
            for (int i = tid; i < CNT; i += 256) stg[i] = src[i];
            __syncthreads();
            int arow = w * 16 + ((grp & 1) ? 8 : 0) + rl;
            u32 abase = S + arow * (CIN * 2) + ((grp >= 2) ? 16 : 0);
#pragma unroll
            for (int kk = 0; kk < KSTEPS; kk++) {
                ldsm4(afr[tap][kk][0], abase + kk * 32);
                ldsm4(afr[tap][kk][1], abase + 128 * CIN * 2 + kk * 32);
            }
        }
        __syncthreads();
    }

    // ---- biases for my C rows ----
    const int r = lane >> 2;                   // frag row 0..7
    const bool isP = !(r & 1);
    const int ch_lo = w * 8 + (r >> 1);
    const int ch_hi = ch_lo + 4;
    float b01, b23;
    {
        int rl0 = r;                            // grow = w*16 + r
        int c8 = w * 8 + (rl0 >> 1);
        b01 = bglob[(rl0 & 1) ? c8 + 64 : c8];
        int rl8 = r + 8;
        c8 = w * 8 + (rl8 >> 1);
        b23 = bglob[(rl8 & 1) ? c8 + 64 : c8];
    }
    const int csub = 2 * (lane & 3);

    const u32 BHI = S;
    const u32 BLO = S + BPLANE;
    const int rowpart = ((grp >= 2) ? 8 : 0) + rl;
    const int bytek = (grp & 1) * 16;

    for (int tile = blockIdx.x; tile < NTILES; tile += gridDim.x) {
        const int tok0 = tile * 64;

        // ---- fill B: rows 0..64 (row = token+1), hi/lo planes ----
        {
            const int NU = 65 * (CIN / 4);
            for (int u = tid; u < NU; u += 256) {
                int rr = u / (CIN / 4);
                int ci0 = (u - rr * (CIN / 4)) * 4;
                int token = tok0 + rr - 1;
                int s = token & 15;
                u32 h01 = 0, h23 = 0, l01 = 0, l23 = 0;
                if (rr >= 1 && s < 12) {
                    int nd = token >> 4;
                    const float* xp = xin + (size_t)nd * CIN * 12 + ci0 * 12 + s;
                    unsigned short hb[4], lb[4];
#pragma unroll
                    for (int j = 0; j < 4; j++) {
                        float v = xp[j * 12];
                        __nv_bfloat16 h = __float2bfloat16(v);
                        __nv_bfloat16 l = __float2bfloat16(v - __bfloat162float(h));
                        hb[j] = *(unsigned short*)&h;
                        lb[j] = *(unsigned short*)&l;
                    }
                    h01 = (u32)hb[0] | ((u32)hb[1] << 16);
                    h23 = (u32)hb[2] | ((u32)hb[3] << 16);
                    l01 = (u32)lb[0] | ((u32)lb[1] << 16);
                    l23 = (u32)lb[2] | ((u32)lb[3] << 16);
                }
                u32 off = rr * BSTRIDE + ci0 * 2;
                asm volatile("st.shared.v2.b32 [%0], {%1, %2};" :: "r"(BHI + off), "r"(h01), "r"(h23));
                asm volatile("st.shared.v2.b32 [%0], {%1, %2};" :: "r"(BLO + off), "r"(l01), "r"(l23));
            }
        }
        __syncthreads();

        // ---- mma: per n-pair, 3 taps x ksteps x {hihi, hilo, lohi} ----
#pragma unroll 1
        for (int np = 0; np < 4; np++) {
            float acc0[4] = { b01, b01, b23, b23 };
            float acc1[4] = { b01, b01, b23, b23 };
#pragma unroll
            for (int tap = 0; tap < 3; tap++) {
                u32 rowoff = (np * 16 + rowpart + tap) * BSTRIDE + bytek;
#pragma unroll
                for (int kk = 0; kk < KSTEPS; kk++) {
                    u32 bh[4], bl[4];
                    ldsm4(bh, BHI + rowoff + kk * 32);
                    ldsm4(bl, BLO + rowoff + kk * 32);
                    mma16816(acc0, afr[tap][kk][0], bh[0], bh[1]);
                    mma16816(acc1, afr[tap][kk][0], bh[2], bh[3]);
                    mma16816(acc0, afr[tap][kk][0], bl[0], bl[1]);
                    mma16816(acc1, afr[tap][kk][0], bl[2], bl[3]);
                    mma16816(acc0, afr[tap][kk][1], bh[0], bh[1]);
                    mma16816(acc1, afr[tap][kk][1], bh[2], bh[3]);
                }
            }
            // ---- epilogue: P*sigmoid(Q), P rows even / Q rows odd ----
#pragma unroll
            for (int i = 0; i < 2; i++) {
                float* acc = i ? acc1 : acc0;
                float q0 = __shfl_down_sync(0xffffffffu, acc[0], 4);
                float q1 = __shfl_down_sync(0xffffffffu, acc[1], 4);
                float q2 = __shfl_down_sync(0xffffffffu, acc[2], 4);
                float q3 = __shfl_down_sync(0xffffffffu, acc[3], 4);
                if (isP) {
                    int c = (2 * np + i) * 8 + csub;
                    int gt = tok0 + c;
                    int s = gt & 15;
                    if (s < 12) {
                        int nd = gt >> 4;
                        float2 o;
                        o.x = acc[0] / (1.0f + __expf(-q0));
                        o.y = acc[1] / (1.0f + __expf(-q1));
                        *(float2*)(xout + (size_t)nd * 768 + ch_lo * 12 + s) = o;
                        o.x = acc[2] / (1.0f + __expf(-q2));
                        o.y = acc[3] / (1.0f + __expf(-q3));
                        *(float2*)(xout + (size_t)nd * 768 + ch_hi * 12 + s) = o;
                    }
                }
            }
        }
        __syncthreads();
    }
}

// ---------------- GCN aggregation (proven, 768-stride) ----------------
__global__ void __launch_bounds__(256) agg_kernel(
        const float* __restrict__ hin, const int* __restrict__ rowptr,
        const int* __restrict__ col, const float* __restrict__ wc,
        float* __restrict__ out)
{
    const int v = blockIdx.x;
    const int tid = threadIdx.x;
    const int beg = rowptr[v], end = rowptr[v + 1];
    float a0 = 0.f, a1 = 0.f, a2 = 0.f;
    __shared__ int scol[64];
    __shared__ float sw[64];
    for (int j0 = beg; j0 < end; j0 += 64) {
        int m = min(64, end - j0);
        if (tid < m) { scol[tid] = col[j0 + tid] * 768; sw[tid] = wc[j0 + tid]; }
        __syncthreads();
#pragma unroll 4
        for (int i = 0; i < m; i++) {
            const float* p = hin + scol[i];
            float w = sw[i];
            a0 = fmaf(w, p[tid], a0);
            a1 = fmaf(w, p[tid + 256], a1);
            a2 = fmaf(w, p[tid + 512], a2);
        }
        __syncthreads();
    }
    float* o = out + (size_t)v * 768;
    o[tid] = a0; o[tid + 256] = a1; o[tid + 512] = a2;
}

// ---------------- GCN transform (proven): out = relu(W @ agg + b) ----------------
__global__ void __launch_bounds__(256) gcn_transform(
        const float* __restrict__ agg, const float* __restrict__ W,
        const float* __restrict__ b, float* __restrict__ out)
{
    const int o = threadIdx.x;
    const int ln = threadIdx.y;
    const int node = blockIdx.x * 4 + ln;
    __shared__ u64 xs[4][64][6];
    __shared__ float Wsh[64][65];

    const float2* ar = (const float2*)(agg + (size_t)node * 768 + o * 12);
#pragma unroll
    for (int j = 0; j < 6; j++) { float2 v = ar[j]; xs[ln][o][j] = pk2(v.x, v.y); }
    for (int i = ln * 64 + o; i < 4096; i += 256) {
        int orow = i >> 6, c = i & 63;
        Wsh[c][orow] = W[i];
    }
    __syncthreads();

    u64 acc[6];
    {
        float bo = b[o];
        u64 b0 = pk2(bo, bo);
#pragma unroll
        for (int j = 0; j < 6; j++) acc[j] = b0;
    }
#pragma unroll 4
    for (int c = 0; c < 64; c++) {
        float w = Wsh[c][o];
        u64 wp = pk2(w, w);
#pragma unroll
        for (int j = 0; j < 6; j++) acc[j] = ffma2(wp, xs[ln][c][j], acc[j]);
    }

    float ov[12];
#pragma unroll
    for (int j = 0; j < 6; j++) {
        float p, q; upk2(acc[j], p, q);
        ov[2 * j]     = fmaxf(p, 0.0f);
        ov[2 * j + 1] = fmaxf(q, 0.0f);
    }
    float4* orow = (float4*)(out + (size_t)node * 768 + o * 12);
#pragma unroll
    for (int j = 0; j < 3; j++)
        orow[j] = make_float4(ov[4 * j], ov[4 * j + 1], ov[4 * j + 2], ov[4 * j + 3]);
}

// ---------------- final conv: warp per node, fw in shared ----------------
__global__ void __launch_bounds__(256) final_conv(
        const float* __restrict__ h, const float* __restrict__ fw,
        const float* __restrict__ fb, float* __restrict__ out)
{
    __shared__ float fws[12 * 768];
    __shared__ float fbs[12];
    const int tid = threadIdx.x;
    for (int i = tid; i < 12 * 768; i += 256) fws[i] = fw[i];
    if (tid < 12) fbs[tid] = fb[tid];
    __syncthreads();

    const int wid = tid >> 5, lane = tid & 31;
    const int node = blockIdx.x * 8 + wid;

    const float4* hr = (const float4*)(h + (size_t)node * 768) + lane * 6;
    float4 hv[6];
#pragma unroll
    for (int q = 0; q < 6; q++) hv[q] = hr[q];

#pragma unroll 1
    for (int o = 0; o < 12; o++) {
        const float4* wr = (const float4*)(fws + o * 768) + lane * 6;
        float acc = 0.f;
#pragma unroll
        for (int q = 0; q < 6; q++) {
            float4 wv = wr[q];
            acc += hv[q].x * wv.x + hv[q].y * wv.y + hv[q].z * wv.z + hv[q].w * wv.w;
        }
#pragma unroll
        for (int m = 16; m; m >>= 1) acc += __shfl_xor_sync(0xffffffffu, acc, m);
        if (lane == o) out[node * 12 + o] = acc + fbs[o];
    }
}

// ---------------- launch ----------------
extern "C" void kernel_launch(void* const* d_in, const int* in_sizes, int n_in,
                              void* d_out, int out_size) {
    const float* x      = (const float*)d_in[0];
    const int*   ei     = (const int*)d_in[1];
    const float* ew     = (const float*)d_in[2];
    const float* tc1a_w = (const float*)d_in[3];
    const float* tc1a_b = (const float*)d_in[4];
    const float* gc1_w  = (const float*)d_in[5];
    const float* gc1_b  = (const float*)d_in[6];
    const float* tc1b_w = (const float*)d_in[7];
    const float* tc1b_b = (const float*)d_in[8];
    const float* tc2a_w = (const float*)d_in[9];
    const float* tc2a_b = (const float*)d_in[10];
    const float* gc2_w  = (const float*)d_in[11];
    const float* gc2_b  = (const float*)d_in[12];
    const float* tc2b_w = (const float*)d_in[13];
    const float* tc2b_b = (const float*)d_in[14];
    const float* fin_w  = (const float*)d_in[15];
    const float* fin_b  = (const float*)d_in[16];

    const int* src = ei;
    const int* dst = ei + EE;

    float *bufA, *bufB, *deg, *dis, *wc;
    int *cnt, *fill, *rowptr, *col;
    uint4 *wA1, *wA2, *wA3, *wA4;
    cudaGetSymbolAddress((void**)&bufA,   g_bufA);
    cudaGetSymbolAddress((void**)&bufB,   g_bufB);
    cudaGetSymbolAddress((void**)&deg,    g_deg);
    cudaGetSymbolAddress((void**)&dis,    g_dis);
    cudaGetSymbolAddress((void**)&wc,     g_wc);
    cudaGetSymbolAddress((void**)&cnt,    g_cnt);
    cudaGetSymbolAddress((void**)&fill,   g_fill);
    cudaGetSymbolAddress((void**)&rowptr, g_rowptr);
    cudaGetSymbolAddress((void**)&col,    g_col);
    cudaGetSymbolAddress((void**)&wA1,    g_wA1);
    cudaGetSymbolAddress((void**)&wA2,    g_wA2);
    cudaGetSymbolAddress((void**)&wA3,    g_wA3);
    cudaGetSymbolAddress((void**)&wA4,    g_wA4);

    // smem: max(A stage for one tap, both planes of B)
    const int SMEM32 = 16640;   // stage 16384, B 2*5376=10752
    const int SMEM64 = 33024;   // stage 32768, B 2*9600=19200
    cudaFuncSetAttribute(conv_mma<32>, cudaFuncAttributeMaxDynamicSharedMemorySize, SMEM32);
    cudaFuncSetAttribute(conv_mma<64>, cudaFuncAttributeMaxDynamicSharedMemorySize, SMEM64);

    // Keep conv1 at launch index 3 — the slot ncu's fixed "-s 5 -c 1" lands on.
    prepack_mma<<<(3 * 2 * 128 * 32 + 255) / 256, 256>>>(tc1a_w, (unsigned short*)wA1, 32); // 0
    csr_init<<<(NN + 255) / 256, 256>>>(cnt, deg, fill);                                    // 1
    csr_count<<<(EE + 255) / 256, 256>>>(dst, ew, cnt, deg);                                // 2
    conv_mma<32><<<148, 256, SMEM32>>>(wA1, tc1a_b, x, bufA);                               // 3 <- profiled
    csr_dis<<<(NN + 255) / 256, 256>>>(deg, dis);                                           // 4
    scan_kernel<<<1, 1024>>>(cnt, rowptr);                                                  // 5
    csr_fill<<<(EE + NN + 255) / 256, 256>>>(src, dst, ew, dis, rowptr, fill, col, wc);
    prepack_mma<<<(3 * 2 * 128 * 64 + 255) / 256, 256>>>(tc1b_w, (unsigned short*)wA2, 64);
    prepack_mma<<<(3 * 2 * 128 * 64 + 255) / 256, 256>>>(tc2a_w, (unsigned short*)wA3, 64);
    prepack_mma<<<(3 * 2 * 128 * 64 + 255) / 256, 256>>>(tc2b_w, (unsigned short*)wA4, 64);

    dim3 tb(64, 4);
    // block 1 (conv1 already launched above)
    agg_kernel<<<NN, 256>>>(bufA, rowptr, col, wc, bufB);
    gcn_transform<<<NN / 4, tb>>>(bufB, gc1_w, gc1_b, bufA);
    conv_mma<64><<<148, 256, SMEM64>>>(wA2, tc1b_b, bufA, bufB);
    // block 2
    conv_mma<64><<<148, 256, SMEM64>>>(wA3, tc2a_b, bufB, bufA);
    agg_kernel<<<NN, 256>>>(bufA, rowptr, col, wc, bufB);
    gcn_transform<<<NN / 4, tb>>>(bufB, gc2_w, gc2_b, bufA);
    conv_mma<64><<<148, 256, SMEM64>>>(wA4, tc2b_b, bufA, bufB);
    // head
    final_conv<<<NN / 8, 256>>>(bufB, fin_w, fin_b, (float*)d_out);
}

// round 16
// speedup vs baseline: 1.3519x; 1.1668x over previous
#include <cuda_runtime.h>
#include <cuda_bf16.h>
#include <math.h>
#include <stdint.h>

#define NN 10000
#define EE 160000
#define NTILES 1250            // 160000 padded tokens / 128

typedef unsigned long long u64;
typedef unsigned int u32;

// ---------------- scratch (device globals; no allocation allowed) ----------------
__device__ float g_bufA[NN * 64 * 12];
__device__ float g_bufB[NN * 64 * 12];
__device__ int   g_cnt[NN];
__device__ int   g_fill[NN];
__device__ int   g_rowptr[NN + 1];
__device__ int   g_col[EE + NN];
__device__ float g_deg[NN];
__device__ float g_dis[NN];
__device__ float g_wc[EE + NN];
// prepacked bf16 conv weights: [tap][plane hi/lo][grow 128][ci CIN]
__device__ uint4 g_wA1[3072];   // CIN=32: 3*2*128*32*2B
__device__ uint4 g_wA2[6144];   // CIN=64
__device__ uint4 g_wA3[6144];
__device__ uint4 g_wA4[6144];

// ---------------- helpers ----------------
__device__ __forceinline__ u64 pk2(float a, float b) {
    u64 r; asm("mov.b64 %0, {%1, %2};" : "=l"(r) : "f"(a), "f"(b)); return r;
}
__device__ __forceinline__ void upk2(u64 v, float& a, float& b) {
    asm("mov.b64 {%0, %1}, %2;" : "=f"(a), "=f"(b) : "l"(v));
}
__device__ __forceinline__ u64 ffma2(u64 a, u64 b, u64 c) {
    u64 d; asm("fma.rn.f32x2 %0, %1, %2, %3;" : "=l"(d) : "l"(a), "l"(b), "l"(c)); return d;
}
__device__ __forceinline__ u32 smem_u32(const void* p) {
    u32 a;
    asm("{ .reg .u64 t; cvta.to.shared.u64 t, %1; cvt.u32.u64 %0, t; }" : "=r"(a) : "l"(p));
    return a;
}
__device__ __forceinline__ void ldsm4(u32 r[4], u32 addr) {
    asm volatile("ldmatrix.sync.aligned.m8n8.x4.shared.b16 {%0,%1,%2,%3}, [%4];"
                 : "=r"(r[0]), "=r"(r[1]), "=r"(r[2]), "=r"(r[3]) : "r"(addr));
}
__device__ __forceinline__ void mma16816(float c[4], const u32 a[4], const u32 b0, const u32 b1) {
    asm volatile("mma.sync.aligned.m16n8k16.row.col.f32.bf16.bf16.f32 "
                 "{%0,%1,%2,%3}, {%4,%5,%6,%7}, {%8,%9}, {%0,%1,%2,%3};"
                 : "+f"(c[0]), "+f"(c[1]), "+f"(c[2]), "+f"(c[3])
                 : "r"(a[0]), "r"(a[1]), "r"(a[2]), "r"(a[3]), "r"(b0), "r"(b1));
}

// ---------------- CSR build (proven) ----------------
__global__ void csr_init(int* cnt, float* deg, int* fill) {
    int v = blockIdx.x * blockDim.x + threadIdx.x;
    if (v < NN) { cnt[v] = 1; deg[v] = 1.0f; fill[v] = 0; }
}
__global__ void csr_count(const int* __restrict__ dst, const float* __restrict__ ew,
                          int* cnt, float* deg) {
    int e = blockIdx.x * blockDim.x + threadIdx.x;
    if (e < EE) {
        int d = dst[e];
        atomicAdd(&cnt[d], 1);
        atomicAdd(&deg[d], ew[e]);
    }
}
__global__ void csr_dis(const float* __restrict__ deg, float* dis) {
    int v = blockIdx.x * blockDim.x + threadIdx.x;
    if (v < NN) dis[v] = rsqrtf(deg[v]);
}
__global__ void scan_kernel(const int* __restrict__ cnt, int* __restrict__ rowptr) {
    __shared__ int part[1024];
    const int tid = threadIdx.x;
    const int CHUNK = 10;
    int base = tid * CHUNK;
    int local[CHUNK];
    int s = 0;
#pragma unroll
    for (int i = 0; i < CHUNK; i++) {
        int idx = base + i;
        int v = (idx < NN) ? cnt[idx] : 0;
        local[i] = s;
        s += v;
    }
    part[tid] = s;
    __syncthreads();
    for (int off = 1; off < 1024; off <<= 1) {
        int v = (tid >= off) ? part[tid - off] : 0;
        __syncthreads();
        part[tid] += v;
        __syncthreads();
    }
    int offset = (tid > 0) ? part[tid - 1] : 0;
#pragma unroll
    for (int i = 0; i < CHUNK; i++) {
        int idx = base + i;
        if (idx <= NN) rowptr[idx] = offset + local[i];
    }
}
__global__ void csr_fill(const int* __restrict__ src, const int* __restrict__ dst,
                         const float* __restrict__ ew, const float* __restrict__ dis,
                         const int* __restrict__ rowptr, int* fill,
                         int* __restrict__ col, float* __restrict__ wc) {
    int i = blockIdx.x * blockDim.x + threadIdx.x;
    if (i < EE) {
        int s = src[i], d = dst[i];
        int pos = rowptr[d] + atomicAdd(&fill[d], 1);
        col[pos] = s;
        wc[pos] = dis[s] * ew[i] * dis[d];
    } else if (i < EE + NN) {
        int v = i - EE;
        int pos = rowptr[v] + atomicAdd(&fill[v], 1);
        col[pos] = v;
        wc[pos] = dis[v] * dis[v];
    }
}

// ---------------- conv weight prepack for mma ----------------
__global__ void prepack_mma(const float* __restrict__ w, unsigned short* __restrict__ wA,
                            int cin) {
    int i = blockIdx.x * blockDim.x + threadIdx.x;
    int total = 3 * 2 * 128 * cin;
    if (i >= total) return;
    int tap = i / (2 * 128 * cin);
    int r = i - tap * (2 * 128 * cin);
    int plane = r / (128 * cin); r -= plane * (128 * cin);
    int grow = r / cin;
    int ci = r - grow * cin;
    int rl = grow & 15;
    int ch8 = (grow >> 4) * 8 + (rl >> 1);
    int co = (rl & 1) ? ch8 + 64 : ch8;
    float v = w[co * cin * 3 + ci * 3 + tap];
    __nv_bfloat16 hi = __float2bfloat16(v);
    if (plane == 0) {
        wA[i] = *(unsigned short*)&hi;
    } else {
        __nv_bfloat16 lo = __float2bfloat16(v - __bfloat162float(hi));
        wA[i] = *(unsigned short*)&lo;
    }
}

// ---------------- gated temporal conv via mma.sync bf16 ----------------
// Tile = 128 tokens (8 nodes), 512 threads / 16 warps.
// Warp w: channel-group (w&7)*8, token-half (w>>3)*64. One shared B tile of
// 130 rows (row = token - tok0 + 1; rows 0 and 129 are boundary taps).
template <int CIN>
__global__ void __launch_bounds__(512, 1) conv_mma(
        const uint4* __restrict__ wA, const float* __restrict__ bglob,
        const float* __restrict__ xin,   // [node][CIN][12]
        float* __restrict__ xout)        // [node][64][12]
{
    constexpr int KSTEPS = CIN / 16;
    constexpr int BSTRIDE = (CIN + 8) * 2;          // bytes per B row (conflict-free)
    constexpr int BPLANE = ((130 * BSTRIDE + 127) / 128) * 128;
    constexpr int STAGE_BYTES = 2 * 128 * CIN * 2;  // one tap, both planes

    extern __shared__ char sm[];
    const u32 S = smem_u32(sm);
    const int tid = threadIdx.x;
    const int w = tid >> 5;
    const int wch = w & 7;                      // channel group
    const int half = w >> 3;                    // token half (0: tok 0-63, 1: 64-127)
    const int lane = tid & 31;
    const int grp = lane >> 3;
    const int rl = lane & 7;

    // ---- stage A per tap, ldmatrix into registers ----
    u32 afr[3][KSTEPS][2][4];
    {
        uint4* stg = (uint4*)sm;
        const int CNT = STAGE_BYTES / 16;
        for (int tap = 0; tap < 3; tap++) {
            __syncthreads();
            const uint4* src = wA + tap * CNT;
            for (int i = tid; i < CNT; i += 512) stg[i] = src[i];
            __syncthreads();
            int arow = wch * 16 + ((grp & 1) ? 8 : 0) + rl;
            u32 abase = S + arow * (CIN * 2) + ((grp >= 2) ? 16 : 0);
#pragma unroll
            for (int kk = 0; kk < KSTEPS; kk++) {
                ldsm4(afr[tap][kk][0], abase + kk * 32);
                ldsm4(afr[tap][kk][1], abase + 128 * CIN * 2 + kk * 32);
            }
        }
        __syncthreads();
    }

    // ---- biases for my C rows ----
    const int r = lane >> 2;                   // frag row 0..7
    const bool isP = !(r & 1);
    const int ch_lo = wch * 8 + (r >> 1);
    const int ch_hi = ch_lo + 4;
    float b01, b23;
    {
        int c8 = wch * 8 + (r >> 1);
        b01 = bglob[(r & 1) ? c8 + 64 : c8];
        int rl8 = r + 8;
        c8 = wch * 8 + (rl8 >> 1);
        b23 = bglob[(rl8 & 1) ? c8 + 64 : c8];
    }
    const int csub = 2 * (lane & 3);

    const u32 BHI = S;
    const u32 BLO = S + BPLANE;
    const int rowpart = half * 64 + ((grp >= 2) ? 8 : 0) + rl;
    const int bytek = (grp & 1) * 16;

    for (int tile = blockIdx.x; tile < NTILES; tile += gridDim.x) {
        const int tok0 = tile * 128;

        // ---- fill B: rows 0..129 (row = token - tok0 + 1), hi/lo planes ----
        {
            const int NU = 130 * (CIN / 4);
            for (int u = tid; u < NU; u += 512) {
                int rr = u / (CIN / 4);
                int ci0 = (u - rr * (CIN / 4)) * 4;
                int token = tok0 + rr - 1;
                int s = token & 15;
                u32 h01 = 0, h23 = 0, l01 = 0, l23 = 0;
                if (rr >= 1 && token < EE && s < 12) {
                    int nd = token >> 4;
                    const float* xp = xin + (size_t)nd * CIN * 12 + ci0 * 12 + s;
                    unsigned short hb[4], lb[4];
#pragma unroll
                    for (int j = 0; j < 4; j++) {
                        float v = xp[j * 12];
                        __nv_bfloat16 h = __float2bfloat16(v);
                        __nv_bfloat16 l = __float2bfloat16(v - __bfloat162float(h));
                        hb[j] = *(unsigned short*)&h;
                        lb[j] = *(unsigned short*)&l;
                    }
                    h01 = (u32)hb[0] | ((u32)hb[1] << 16);
                    h23 = (u32)hb[2] | ((u32)hb[3] << 16);
                    l01 = (u32)lb[0] | ((u32)lb[1] << 16);
                    l23 = (u32)lb[2] | ((u32)lb[3] << 16);
                }
                u32 off = rr * BSTRIDE + ci0 * 2;
                asm volatile("st.shared.v2.b32 [%0], {%1, %2};" :: "r"(BHI + off), "r"(h01), "r"(h23));
                asm volatile("st.shared.v2.b32 [%0], {%1, %2};" :: "r"(BLO + off), "r"(l01), "r"(l23));
            }
        }
        __syncthreads();

        // ---- mma: per n-pair, 3 taps x ksteps x {hihi, hilo, lohi} ----
#pragma unroll 1
        for (int np = 0; np < 4; np++) {
            float acc0[4] = { b01, b01, b23, b23 };
            float acc1[4] = { b01, b01, b23, b23 };
#pragma unroll
            for (int tap = 0; tap < 3; tap++) {
                u32 rowoff = (np * 16 + rowpart + tap) * BSTRIDE + bytek;
#pragma unroll
                for (int kk = 0; kk < KSTEPS; kk++) {
                    u32 bh[4], bl[4];
                    ldsm4(bh, BHI + rowoff + kk * 32);
                    ldsm4(bl, BLO + rowoff + kk * 32);
                    mma16816(acc0, afr[tap][kk][0], bh[0], bh[1]);
                    mma16816(acc1, afr[tap][kk][0], bh[2], bh[3]);
                    mma16816(acc0, afr[tap][kk][0], bl[0], bl[1]);
                    mma16816(acc1, afr[tap][kk][0], bl[2], bl[3]);
                    mma16816(acc0, afr[tap][kk][1], bh[0], bh[1]);
                    mma16816(acc1, afr[tap][kk][1], bh[2], bh[3]);
                }
            }
            // ---- epilogue: P*sigmoid(Q), P rows even / Q rows odd ----
#pragma unroll
            for (int i = 0; i < 2; i++) {
                float* acc = i ? acc1 : acc0;
                float q0 = __shfl_down_sync(0xffffffffu, acc[0], 4);
                float q1 = __shfl_down_sync(0xffffffffu, acc[1], 4);
                float q2 = __shfl_down_sync(0xffffffffu, acc[2], 4);
                float q3 = __shfl_down_sync(0xffffffffu, acc[3], 4);
                if (isP) {
                    int c = half * 64 + (2 * np + i) * 8 + csub;
                    int gt = tok0 + c;
                    int s = gt & 15;
                    if (s < 12) {
                        int nd = gt >> 4;
                        float2 o;
                        o.x = acc[0] / (1.0f + __expf(-q0));
                        o.y = acc[1] / (1.0f + __expf(-q1));
                        *(float2*)(xout + (size_t)nd * 768 + ch_lo * 12 + s) = o;
                        o.x = acc[2] / (1.0f + __expf(-q2));
                        o.y = acc[3] / (1.0f + __expf(-q3));
                        *(float2*)(xout + (size_t)nd * 768 + ch_hi * 12 + s) = o;
                    }
                }
            }
        }
        __syncthreads();
    }
}

// ---------------- GCN aggregation (proven, 768-stride) ----------------
__global__ void __launch_bounds__(256) agg_kernel(
        const float* __restrict__ hin, const int* __restrict__ rowptr,
        const int* __restrict__ col, const float* __restrict__ wc,
        float* __restrict__ out)
{
    const int v = blockIdx.x;
    const int tid = threadIdx.x;
    const int beg = rowptr[v], end = rowptr[v + 1];
    float a0 = 0.f, a1 = 0.f, a2 = 0.f;
    __shared__ int scol[64];
    __shared__ float sw[64];
    for (int j0 = beg; j0 < end; j0 += 64) {
        int m = min(64, end - j0);
        if (tid < m) { scol[tid] = col[j0 + tid] * 768; sw[tid] = wc[j0 + tid]; }
        __syncthreads();
#pragma unroll 4
        for (int i = 0; i < m; i++) {
            const float* p = hin + scol[i];
            float w = sw[i];
            a0 = fmaf(w, p[tid], a0);
            a1 = fmaf(w, p[tid + 256], a1);
            a2 = fmaf(w, p[tid + 512], a2);
        }
        __syncthreads();
    }
    float* o = out + (size_t)v * 768;
    o[tid] = a0; o[tid + 256] = a1; o[tid + 512] = a2;
}

// ---------------- GCN transform (proven): out = relu(W @ agg + b) ----------------
__global__ void __launch_bounds__(256) gcn_transform(
        const float* __restrict__ agg, const float* __restrict__ W,
        const float* __restrict__ b, float* __restrict__ out)
{
    const int o = threadIdx.x;
    const int ln = threadIdx.y;
    const int node = blockIdx.x * 4 + ln;
    __shared__ u64 xs[4][64][6];
    __shared__ float Wsh[64][65];

    const float2* ar = (const float2*)(agg + (size_t)node * 768 + o * 12);
#pragma unroll
    for (int j = 0; j < 6; j++) { float2 v = ar[j]; xs[ln][o][j] = pk2(v.x, v.y); }
    for (int i = ln * 64 + o; i < 4096; i += 256) {
        int orow = i >> 6, c = i & 63;
        Wsh[c][orow] = W[i];
    }
    __syncthreads();

    u64 acc[6];
    {
        float bo = b[o];
        u64 b0 = pk2(bo, bo);
#pragma unroll
        for (int j = 0; j < 6; j++) acc[j] = b0;
    }
#pragma unroll 4
    for (int c = 0; c < 64; c++) {
        float w = Wsh[c][o];
        u64 wp = pk2(w, w);
#pragma unroll
        for (int j = 0; j < 6; j++) acc[j] = ffma2(wp, xs[ln][c][j], acc[j]);
    }

    float ov[12];
#pragma unroll
    for (int j = 0; j < 6; j++) {
        float p, q; upk2(acc[j], p, q);
        ov[2 * j]     = fmaxf(p, 0.0f);
        ov[2 * j + 1] = fmaxf(q, 0.0f);
    }
    float4* orow = (float4*)(out + (size_t)node * 768 + o * 12);
#pragma unroll
    for (int j = 0; j < 3; j++)
        orow[j] = make_float4(ov[4 * j], ov[4 * j + 1], ov[4 * j + 2], ov[4 * j + 3]);
}

// ---------------- final conv: warp per node, fw in shared ----------------
__global__ void __launch_bounds__(256) final_conv(
        const float* __restrict__ h, const float* __restrict__ fw,
        const float* __restrict__ fb, float* __restrict__ out)
{
    __shared__ float fws[12 * 768];
    __shared__ float fbs[12];
    const int tid = threadIdx.x;
    for (int i = tid; i < 12 * 768; i += 256) fws[i] = fw[i];
    if (tid < 12) fbs[tid] = fb[tid];
    __syncthreads();

    const int wid = tid >> 5, lane = tid & 31;
    const int node = blockIdx.x * 8 + wid;

    const float4* hr = (const float4*)(h + (size_t)node * 768) + lane * 6;
    float4 hv[6];
#pragma unroll
    for (int q = 0; q < 6; q++) hv[q] = hr[q];

#pragma unroll 1
    for (int o = 0; o < 12; o++) {
        const float4* wr = (const float4*)(fws + o * 768) + lane * 6;
        float acc = 0.f;
#pragma unroll
        for (int q = 0; q < 6; q++) {
            float4 wv = wr[q];
            acc += hv[q].x * wv.x + hv[q].y * wv.y + hv[q].z * wv.z + hv[q].w * wv.w;
        }
#pragma unroll
        for (int m = 16; m; m >>= 1) acc += __shfl_xor_sync(0xffffffffu, acc, m);
        if (lane == o) out[node * 12 + o] = acc + fbs[o];
    }
}

// ---------------- launch ----------------
extern "C" void kernel_launch(void* const* d_in, const int* in_sizes, int n_in,
                              void* d_out, int out_size) {
    const float* x      = (const float*)d_in[0];
    const int*   ei     = (const int*)d_in[1];
    const float* ew     = (const float*)d_in[2];
    const float* tc1a_w = (const float*)d_in[3];
    const float* tc1a_b = (const float*)d_in[4];
    const float* gc1_w  = (const float*)d_in[5];
    const float* gc1_b  = (const float*)d_in[6];
    const float* tc1b_w = (const float*)d_in[7];
    const float* tc1b_b = (const float*)d_in[8];
    const float* tc2a_w = (const float*)d_in[9];
    const float* tc2a_b = (const float*)d_in[10];
    const float* gc2_w  = (const float*)d_in[11];
    const float* gc2_b  = (const float*)d_in[12];
    const float* tc2b_w = (const float*)d_in[13];
    const float* tc2b_b = (const float*)d_in[14];
    const float* fin_w  = (const float*)d_in[15];
    const float* fin_b  = (const float*)d_in[16];

    const int* src = ei;
    const int* dst = ei + EE;

    float *bufA, *bufB, *deg, *dis, *wc;
    int *cnt, *fill, *rowptr, *col;
    uint4 *wA1, *wA2, *wA3, *wA4;
    cudaGetSymbolAddress((void**)&bufA,   g_bufA);
    cudaGetSymbolAddress((void**)&bufB,   g_bufB);
    cudaGetSymbolAddress((void**)&deg,    g_deg);
    cudaGetSymbolAddress((void**)&dis,    g_dis);
    cudaGetSymbolAddress((void**)&wc,     g_wc);
    cudaGetSymbolAddress((void**)&cnt,    g_cnt);
    cudaGetSymbolAddress((void**)&fill,   g_fill);
    cudaGetSymbolAddress((void**)&rowptr, g_rowptr);
    cudaGetSymbolAddress((void**)&col,    g_col);
    cudaGetSymbolAddress((void**)&wA1,    g_wA1);
    cudaGetSymbolAddress((void**)&wA2,    g_wA2);
    cudaGetSymbolAddress((void**)&wA3,    g_wA3);
    cudaGetSymbolAddress((void**)&wA4,    g_wA4);

    // smem: max(A stage for one tap, both planes of B)
    const int SMEM32 = 20992;   // stage 16384, B 2*10496
    const int SMEM64 = 37632;   // stage 32768, B 2*18816
    cudaFuncSetAttribute(conv_mma<32>, cudaFuncAttributeMaxDynamicSharedMemorySize, SMEM32);
    cudaFuncSetAttribute(conv_mma<64>, cudaFuncAttributeMaxDynamicSharedMemorySize, SMEM64);

    // Keep conv1 at launch index 3 — the slot ncu's fixed "-s 5 -c 1" lands on.
    prepack_mma<<<(3 * 2 * 128 * 32 + 255) / 256, 256>>>(tc1a_w, (unsigned short*)wA1, 32); // 0
    csr_init<<<(NN + 255) / 256, 256>>>(cnt, deg, fill);                                    // 1
    csr_count<<<(EE + 255) / 256, 256>>>(dst, ew, cnt, deg);                                // 2
    conv_mma<32><<<148, 512, SMEM32>>>(wA1, tc1a_b, x, bufA);                               // 3 <- profiled
    csr_dis<<<(NN + 255) / 256, 256>>>(deg, dis);                                           // 4
    scan_kernel<<<1, 1024>>>(cnt, rowptr);                                                  // 5
    csr_fill<<<(EE + NN + 255) / 256, 256>>>(src, dst, ew, dis, rowptr, fill, col, wc);
    prepack_mma<<<(3 * 2 * 128 * 64 + 255) / 256, 256>>>(tc1b_w, (unsigned short*)wA2, 64);
    prepack_mma<<<(3 * 2 * 128 * 64 + 255) / 256, 256>>>(tc2a_w, (unsigned short*)wA3, 64);
    prepack_mma<<<(3 * 2 * 128 * 64 + 255) / 256, 256>>>(tc2b_w, (unsigned short*)wA4, 64);

    dim3 tb(64, 4);
    // block 1 (conv1 already launched above)
    agg_kernel<<<NN, 256>>>(bufA, rowptr, col, wc, bufB);
    gcn_transform<<<NN / 4, tb>>>(bufB, gc1_w, gc1_b, bufA);
    conv_mma<64><<<148, 512, SMEM64>>>(wA2, tc1b_b, bufA, bufB);
    // block 2
    conv_mma<64><<<148, 512, SMEM64>>>(wA3, tc2a_b, bufB, bufA);
    agg_kernel<<<NN, 256>>>(bufA, rowptr, col, wc, bufB);
    gcn_transform<<<NN / 4, tb>>>(bufB, gc2_w, gc2_b, bufA);
    conv_mma<64><<<148, 512, SMEM64>>>(wA4, tc2b_b, bufA, bufB);
    // head
    final_conv<<<NN / 8, 256>>>(bufB, fin_w, fin_b, (float*)d_out);
}